// round 11
// baseline (speedup 1.0000x reference)
#include <cuda_runtime.h>
#include <cstdint>

#define DD 128
#define KK 32
#define NTHREADS 512
#define NBLOCKS 444
#define NCELLS 128

// ---- shared memory layout ----
// Dim slots swizzled: logical dim d -> slot sd = (d&3)*32 + (d>>2); a lane
// owning logical dims 4*lane..4*lane+3 touches slots 32*i+lane (bank=lane),
// conflict-free for every table at any bin index.
// s_x   : float [33][128]   knot x positions (scalar LDS.32)
// s_ys  : float2[33][128]   {y_k, slope_k}   (LDS.64, 2-phase cf)
// s_lutw: uint32[32][128]   4 packed cell-bases per word (1 cf LDS.32)
#define SMEM_BYTES (33 * DD * 4 + 33 * DD * 8 + (NCELLS / 4) * DD * 4)

__global__ void __launch_bounds__(NTHREADS, 3)
rqs_kernel(const float* __restrict__ x,
           const float* __restrict__ sp,
           float* __restrict__ y_out,
           float* __restrict__ ld_out,
           int n_rows)
{
    extern __shared__ float sm[];
    float*    s_x    = sm;
    float2*   s_ys   = (float2*)(sm + 33 * DD);
    uint32_t* s_lutw = (uint32_t*)(s_ys + 33 * DD);

    const int tid = threadIdx.x;
    const float TOTAL_M = 10.0f - KK * 1e-4f;

    // ---- per-block table build (redundant across blocks, trivially cheap) ----
    if (tid < DD) {
        const int d = tid;
        const int sd = (d & 3) * 32 + (d >> 2);        // swizzled slot
        const float* uw = sp + d * (3 * KK + 1);
        float m = -1e30f;
        #pragma unroll 1
        for (int k = 0; k < KK; k++) m = fmaxf(m, uw[k]);
        float s = 0.f;
        #pragma unroll 1
        for (int k = 0; k < KK; k++) s += __expf(uw[k] - m);
        float scale = TOTAL_M / s;
        float run = -5.0f;
        s_x[sd] = run;
        #pragma unroll 1
        for (int k = 0; k < KK; k++) {
            float w = __expf(uw[k] - m) * scale + 1e-4f;
            run += w;
            s_x[(k + 1) * DD + sd] = run;
        }
        // LUT: bin of each cell's left edge (clamped to 28 so base+3 <= 31),
        // packed 4 cells per 32-bit word
        int k = 0;
        uint32_t word = 0;
        #pragma unroll 1
        for (int c = 0; c < NCELLS; c++) {
            float cl = c * 0.078125f - 5.0f;            // exact: 10/128
            while (k < 31 && s_x[(k + 1) * DD + sd] <= cl) k++;
            word |= (uint32_t)min(k, 28) << ((c & 3) * 8);
            if ((c & 3) == 3) { s_lutw[(c >> 2) * DD + sd] = word; word = 0; }
        }
    } else if (tid < 2 * DD) {
        const int d = tid - DD;
        const int sd = (d & 3) * 32 + (d >> 2);
        const float* uh = sp + d * (3 * KK + 1) + KK;
        const float* us = sp + d * (3 * KK + 1) + 2 * KK;
        float m = -1e30f;
        #pragma unroll 1
        for (int k = 0; k < KK; k++) m = fmaxf(m, uh[k]);
        float s = 0.f;
        #pragma unroll 1
        for (int k = 0; k < KK; k++) s += __expf(uh[k] - m);
        float scale = TOTAL_M / s;
        const float OFFS = 0.5411666430f;  // log(expm1(1 - 1e-4))
        float run = -5.0f;
        #pragma unroll 1
        for (int k = 0; k <= KK; k++) {
            float v = us[k] + OFFS;
            float spv = fmaxf(v, 0.f) + __logf(1.f + __expf(-fabsf(v)));
            s_ys[k * DD + sd] = make_float2(run, spv + 1e-4f);
            if (k < KK) run += __expf(uh[k] - m) * scale + 1e-4f;
        }
    }
    __syncthreads();

    // ---- main loop: one warp per row; lane owns logical dims 4*lane+i ----
    const int lane = tid & 31;
    const int warp = (blockIdx.x * NTHREADS + tid) >> 5;
    const int nwarps = gridDim.x * (NTHREADS >> 5);
    const float LN2 = 0.69314718055994531f;

    for (int row = warp; row < n_rows; row += nwarps) {
        const float4 xin = *(const float4*)(x + (unsigned)row * DD + 4 * lane);
        const float xa[4] = {xin.x, xin.y, xin.z, xin.w};
        float yv[4];
        float prod = 1.0f;

        #pragma unroll
        for (int i = 0; i < 4; i++) {
            const int slot = 32 * i + lane;
            const float xv = xa[i];

            // LUT (1 conflict-free LDS.32): conservative (low) bin base
            const int c = (int)fminf(fmaxf(fmaf(xv, 12.8f, 63.0f), 0.0f), 127.0f);
            const uint32_t w = s_lutw[(c >> 2) * DD + slot];
            const int base = (int)((w >> ((c & 3) * 8)) & 0xFF);

            // 3 indicator loads (imm offsets), predicated adds on the offset
            int o = base * DD + slot;
            const float k1 = s_x[o + DD];
            const float k2 = s_x[o + 2 * DD];
            const float k3 = s_x[o + 3 * DD];
            if (xv >= k1) o += DD;
            if (xv >= k2) o += DD;
            if (xv >= k3) o += DD;

            // fetch; rare fixup (128 cells + 3 indicators -> ~1e-5 rate)
            float x0 = s_x[o];
            float x1 = s_x[o + DD];
            while (xv >= x1 && o < (KK - 1) * DD) {    // cold
                o += DD;
                x0 = x1;
                x1 = s_x[o + DD];
            }
            const float2 r0 = s_ys[o];
            const float2 r1 = s_ys[o + DD];
            const float y0 = r0.x, s0 = r0.y;
            const float y1 = r1.x, s1 = r1.y;

            float ib;
            asm("rcp.approx.f32 %0, %1;" : "=f"(ib) : "f"(x1 - x0));
            const float zr   = (xv - x0) * ib;
            const float z    = fminf(fmaxf(zr, 0.f), 1.f);
            const float bh   = y1 - y0;
            const float bs   = bh * ib;
            const float sqz  = z * z;
            const float z1mz = z - sqz;
            const float omz  = 1.f - z;
            const float sq1  = omz * omz;

            const float st  = (s0 + s1) - 2.f * bs;
            const float den = fmaf(st, z1mz, bs);
            const float num = bh * fmaf(s0, z1mz, bs * sqz);

            float r;
            asm("rcp.approx.f32 %0, %1;" : "=f"(r) : "f"(den));
            float yy = fmaf(num, r, y0);

            // deriv = bs^2 * arg / den^2 ; fold bs^2 via t = bs * (1/den)
            const float arg = fmaf(s1, sqz, fmaf(s0, sq1, (bs + bs) * z1mz));
            const float t   = bs * r;
            float deriv = (t * t) * arg;

            // out-of-range tails (P ~ 6e-7): rare branch
            if (zr != z) {
                if (zr < 0.f) {
                    yy = fmaf(xv - x0, s0, y0);
                    deriv = s0;
                } else {
                    yy = fmaf(xv - x1, s1, y1);
                    deriv = s1;
                }
            }
            prod *= deriv;
            yv[i] = yy;
        }

        *(float4*)(y_out + (unsigned)row * DD + 4 * lane) =
            make_float4(yv[0], yv[1], yv[2], yv[3]);

        // one LG2 per 4 elements, then warp-sum; scale by ln2 once per row
        float ls = __log2f(prod);
        #pragma unroll
        for (int off = 16; off; off >>= 1)
            ls += __shfl_xor_sync(0xffffffffu, ls, off);
        if (lane == 0) ld_out[row] = ls * LN2;
    }
}

extern "C" void kernel_launch(void* const* d_in, const int* in_sizes, int n_in,
                              void* d_out, int out_size)
{
    const float* x  = (const float*)d_in[0];
    const float* sp = (const float*)d_in[1];
    const int n_rows = in_sizes[0] / DD;

    float* y_out  = (float*)d_out;
    float* ld_out = (float*)d_out + (size_t)n_rows * DD;

    cudaFuncSetAttribute(rqs_kernel, cudaFuncAttributeMaxDynamicSharedMemorySize,
                         SMEM_BYTES);
    rqs_kernel<<<NBLOCKS, NTHREADS, SMEM_BYTES>>>(x, sp, y_out, ld_out, n_rows);
}

// round 12
// speedup vs baseline: 1.0055x; 1.0055x over previous
#include <cuda_runtime.h>
#include <cstdint>

#define DD 128
#define KK 32
#define NTHREADS 512
#define NBLOCKS 444
#define NCELLS 192
#define CPW (NCELLS / 4)          // packed words per dim

// ---- shared memory layout ----
// Dim slots swizzled: logical dim d -> slot sd = (d&3)*32 + (d>>2); a lane
// owning logical dims 4*lane..4*lane+3 touches slots 32*i+lane (bank=lane),
// conflict-free for every table at any bin index.
// s_x   : float [33][128]  knot x positions (scalar LDS.32)
// s_ys  : float2[33][128]  {y_k, slope_k}
// s_lutw: uint32[48][128]  4 packed cell-bases per word (1 cf LDS.32)
#define SMEM_BYTES (33 * DD * 4 + 33 * DD * 8 + CPW * DD * 4)

__global__ void __launch_bounds__(NTHREADS, 3)
rqs_kernel(const float* __restrict__ x,
           const float* __restrict__ sp,
           float* __restrict__ y_out,
           float* __restrict__ ld_out,
           int n_rows)
{
    extern __shared__ float sm[];
    float*    s_x    = sm;
    float2*   s_ys   = (float2*)(sm + 33 * DD);
    uint32_t* s_lutw = (uint32_t*)(s_ys + 33 * DD);

    const int tid = threadIdx.x;
    const float TOTAL_M = 10.0f - KK * 1e-4f;

    // ---- per-block table build (redundant across blocks, trivially cheap) ----
    if (tid < DD) {
        const int d = tid;
        const int sd = (d & 3) * 32 + (d >> 2);        // swizzled slot
        const float* uw = sp + d * (3 * KK + 1);
        float m = -1e30f;
        #pragma unroll 1
        for (int k = 0; k < KK; k++) m = fmaxf(m, uw[k]);
        float s = 0.f;
        #pragma unroll 1
        for (int k = 0; k < KK; k++) s += __expf(uw[k] - m);
        float scale = TOTAL_M / s;
        float run = -5.0f;
        s_x[sd] = run;
        #pragma unroll 1
        for (int k = 0; k < KK; k++) {
            float w = __expf(uw[k] - m) * scale + 1e-4f;
            run += w;
            s_x[(k + 1) * DD + sd] = run;
        }
        // LUT: bin of each cell's left edge, clamped to 27 so base+4 <= 31;
        // packed 4 cells per 32-bit word (conflict-free LDS.32 in hot path)
        int k = 0;
        uint32_t word = 0;
        #pragma unroll 1
        for (int c = 0; c < NCELLS; c++) {
            float cl = c * (10.0f / NCELLS) - 5.0f;
            while (k < 31 && s_x[(k + 1) * DD + sd] <= cl) k++;
            word |= (uint32_t)min(k, 27) << ((c & 3) * 8);
            if ((c & 3) == 3) { s_lutw[(c >> 2) * DD + sd] = word; word = 0; }
        }
    } else if (tid < 2 * DD) {
        const int d = tid - DD;
        const int sd = (d & 3) * 32 + (d >> 2);
        const float* uh = sp + d * (3 * KK + 1) + KK;
        const float* us = sp + d * (3 * KK + 1) + 2 * KK;
        float m = -1e30f;
        #pragma unroll 1
        for (int k = 0; k < KK; k++) m = fmaxf(m, uh[k]);
        float s = 0.f;
        #pragma unroll 1
        for (int k = 0; k < KK; k++) s += __expf(uh[k] - m);
        float scale = TOTAL_M / s;
        const float OFFS = 0.5411666430f;  // log(expm1(1 - 1e-4))
        float run = -5.0f;
        #pragma unroll 1
        for (int k = 0; k <= KK; k++) {
            float v = us[k] + OFFS;
            float spv = fmaxf(v, 0.f) + __logf(1.f + __expf(-fabsf(v)));
            s_ys[k * DD + sd] = make_float2(run, spv + 1e-4f);
            if (k < KK) run += __expf(uh[k] - m) * scale + 1e-4f;
        }
    }
    __syncthreads();

    // ---- main loop: one warp per row; lane owns logical dims 4*lane+i ----
    const int lane = tid & 31;
    const int warp = (blockIdx.x * NTHREADS + tid) >> 5;
    const int nwarps = gridDim.x * (NTHREADS >> 5);
    const float LN2 = 0.69314718055994531f;

    for (int row = warp; row < n_rows; row += nwarps) {
        const float4 xin = *(const float4*)(x + (unsigned)row * DD + 4 * lane);
        const float xa[4] = {xin.x, xin.y, xin.z, xin.w};
        float yv[4];
        float prod = 1.0f;

        #pragma unroll
        for (int i = 0; i < 4; i++) {
            const int slot = 32 * i + lane;
            const float xv = xa[i];

            // LUT (1 conflict-free LDS.32): conservative (low) bin base.
            // c = floor((xv+5)*19.2) - 1, clamped to [0, NCELLS-1]
            const float cf = fminf(fmaxf(fmaf(xv, 19.2f, 95.0f), 0.0f),
                                   (float)(NCELLS - 1));
            const int c = (int)cf;
            const uint32_t w = s_lutw[(c >> 2) * DD + slot];
            const int base = (int)((w >> ((c & 3) * 8)) & 0xFF);

            // 4 bool-sum indicators (branchless, imm-offset LDS off one reg).
            // 192 cells => >2 knots per cell is absent for this data, and the
            // 4-indicator window covers up to 4 knots past base regardless.
            const int ob = base * DD + slot;
            const int idx = base + (xv >= s_x[ob + 1 * DD])
                                 + (xv >= s_x[ob + 2 * DD])
                                 + (xv >= s_x[ob + 3 * DD])
                                 + (xv >= s_x[ob + 4 * DD]);

            // fetch (all parallel, conflict-free)
            const int o = idx * DD + slot;
            const float  x0 = s_x[o];
            const float  x1 = s_x[o + DD];
            const float2 r0 = s_ys[o];
            const float2 r1 = s_ys[o + DD];
            const float y0 = r0.x, s0 = r0.y;
            const float y1 = r1.x, s1 = r1.y;

            float ib;
            asm("rcp.approx.f32 %0, %1;" : "=f"(ib) : "f"(x1 - x0));
            const float zr   = (xv - x0) * ib;
            const float z    = fminf(fmaxf(zr, 0.f), 1.f);
            const float bh   = y1 - y0;
            const float bs   = bh * ib;
            const float sqz  = z * z;
            const float z1mz = z - sqz;
            const float omz  = 1.f - z;
            const float sq1  = omz * omz;

            const float st  = (s0 + s1) - 2.f * bs;
            const float den = fmaf(st, z1mz, bs);
            const float num = bh * fmaf(s0, z1mz, bs * sqz);

            float r;
            asm("rcp.approx.f32 %0, %1;" : "=f"(r) : "f"(den));
            float yy = fmaf(num, r, y0);

            // deriv = bs^2 * arg / den^2 ; fold bs^2 via t = bs * (1/den)
            const float arg = fmaf(s1, sqz, fmaf(s0, sq1, (bs + bs) * z1mz));
            const float t   = bs * r;
            float deriv = (t * t) * arg;

            // out-of-range tails (P ~ 6e-7): single rare branch
            if (zr != z) {
                if (zr < 0.f) {
                    yy = fmaf(xv - x0, s0, y0);
                    deriv = s0;
                } else {
                    yy = fmaf(xv - x1, s1, y1);
                    deriv = s1;
                }
            }
            prod *= deriv;
            yv[i] = yy;
        }

        *(float4*)(y_out + (unsigned)row * DD + 4 * lane) =
            make_float4(yv[0], yv[1], yv[2], yv[3]);

        // one LG2 per 4 elements, then warp-sum; scale by ln2 once per row
        float ls = __log2f(prod);
        #pragma unroll
        for (int off = 16; off; off >>= 1)
            ls += __shfl_xor_sync(0xffffffffu, ls, off);
        if (lane == 0) ld_out[row] = ls * LN2;
    }
}

extern "C" void kernel_launch(void* const* d_in, const int* in_sizes, int n_in,
                              void* d_out, int out_size)
{
    const float* x  = (const float*)d_in[0];
    const float* sp = (const float*)d_in[1];
    const int n_rows = in_sizes[0] / DD;

    float* y_out  = (float*)d_out;
    float* ld_out = (float*)d_out + (size_t)n_rows * DD;

    cudaFuncSetAttribute(rqs_kernel, cudaFuncAttributeMaxDynamicSharedMemorySize,
                         SMEM_BYTES);
    rqs_kernel<<<NBLOCKS, NTHREADS, SMEM_BYTES>>>(x, sp, y_out, ld_out, n_rows);
}

// round 13
// speedup vs baseline: 1.5342x; 1.5258x over previous
#include <cuda_runtime.h>
#include <cstdint>

#define DD 128
#define KK 32
#define NTHREADS 1024
#define NBLOCKS 148

// ---- shared memory layout (bytes) ----
// Dim slots swizzled: logical dim d -> slot sd=(d&3)*32+(d>>2); lane owns
// logical dims 4*lane..4*lane+3 -> hot slot = 32*i+lane (bank=lane, cf).
// s_x : float [33][128] knot x positions (binary search + cold tails)
// T1  : float4[32][128] {ib, J=-x0*ib, A, B}
// T2  : float4[32][128] {C, R, bs, E}
// T3  : float [32][128] {F}
#define SX_OFF 0
#define T1_OFF 16896
#define T2_OFF (T1_OFF + 32 * DD * 16)
#define T3_OFF (T2_OFF + 32 * DD * 16)
#define SMEM_BYTES (T3_OFF + 32 * DD * 4)

__global__ void __launch_bounds__(NTHREADS, 1)
rqs_kernel(const float* __restrict__ x,
           const float* __restrict__ sp,
           float* __restrict__ y_out,
           float* __restrict__ ld_out,
           int n_rows)
{
    extern __shared__ char smem_raw[];
    float*  s_x = (float*)(smem_raw + SX_OFF);
    float4* s_T1 = (float4*)(smem_raw + T1_OFF);
    float4* s_T2 = (float4*)(smem_raw + T2_OFF);
    float*  s_T3 = (float*)(smem_raw + T3_OFF);

    const int tid = threadIdx.x;
    const float TOTAL_M = 10.0f - KK * 1e-4f;
    const float OFFS = 0.5411666430f;  // log(expm1(1 - 1e-4))

    // ---- per-block table build: one thread per dim, streaming ----
    if (tid < DD) {
        const int d = tid;
        const int sd = (d & 3) * 32 + (d >> 2);
        const float* uw = sp + d * (3 * KK + 1);
        const float* uh = uw + KK;
        const float* us = uw + 2 * KK;

        float mw = -1e30f, mh = -1e30f;
        #pragma unroll 1
        for (int k = 0; k < KK; k++) { mw = fmaxf(mw, uw[k]); mh = fmaxf(mh, uh[k]); }
        float sw = 0.f, sh = 0.f;
        #pragma unroll 1
        for (int k = 0; k < KK; k++) { sw += __expf(uw[k] - mw); sh += __expf(uh[k] - mh); }
        const float scw = TOTAL_M / sw;
        const float sch = TOTAL_M / sh;

        float x0 = -5.0f, y0 = -5.0f;
        float v0 = us[0] + OFFS;
        float s0 = fmaxf(v0, 0.f) + __logf(1.f + __expf(-fabsf(v0))) + 1e-4f;
        s_x[sd] = x0;

        #pragma unroll 1
        for (int k = 0; k < KK; k++) {
            const float w = __expf(uw[k] - mw) * scw + 1e-4f;
            const float h = __expf(uh[k] - mh) * sch + 1e-4f;
            const float x1 = x0 + w;
            const float y1 = y0 + h;
            const float vk = us[k + 1] + OFFS;
            const float s1 = fmaxf(vk, 0.f) + __logf(1.f + __expf(-fabsf(vk))) + 1e-4f;

            const float wd = x1 - x0;          // match reference re-diff
            const float ib = 1.0f / wd;
            const float bh = y1 - y0;
            const float bs = bh / wd;
            const float R  = (s0 + s1) - 2.0f * bs;

            const float A = bh * bs - bh * s0 - y0 * R;
            const float B = bh * s0 + y0 * R;
            const float C = y0 * bs;
            const float E = s1 - s0;
            const float F = s0 + bs;
            const float J = -x0 * ib;

            s_x[(k + 1) * DD + sd] = x1;
            s_T1[k * DD + sd] = make_float4(ib, J, A, B);
            s_T2[k * DD + sd] = make_float4(C, R, bs, E);
            s_T3[k * DD + sd] = F;

            x0 = x1; y0 = y1; s0 = s1;
        }
    }
    __syncthreads();

    // ---- main loop: one warp per row; lane owns logical dims 4*lane+i ----
    const int lane = tid & 31;
    const int warp = (blockIdx.x * NTHREADS + tid) >> 5;
    const int nwarps = NBLOCKS * (NTHREADS >> 5);
    const float LN2 = 0.69314718055994531f;

    for (int row = warp; row < n_rows; row += nwarps) {
        const float4 xin = *(const float4*)(x + (unsigned)row * DD + 4 * lane);
        const float xa[4] = {xin.x, xin.y, xin.z, xin.w};
        float yv[4];
        float prod = 1.0f;

        #pragma unroll
        for (int i = 0; i < 4; i++) {
            const int slot = 32 * i + lane;
            const float xv = xa[i];

            // binary search (R2 form, no x0 tracking): largest idx with
            // x_pos[idx] <= xv, idx in [0,31]
            int idx = 0;
            #pragma unroll
            for (int step = 16; step; step >>= 1) {
                if (xv >= s_x[(idx + step) * DD + slot]) idx += step;
            }
            const int o = idx * DD + slot;

            // fetch: 2x LDS.128 + 1x LDS.32
            const float4 t1 = s_T1[o];   // {ib, J, A, B}
            const float4 t2 = s_T2[o];   // {C, R, bs, E}
            const float  F  = s_T3[o];

            const float zr = fmaf(xv, t1.x, t1.y);          // (xv-x0)*ib
            const float z  = fminf(fmaxf(zr, 0.f), 1.f);
            const float v  = z * z;

            const float Nz  = fmaf(t1.z, v, fmaf(t1.w, z, t2.x));
            const float den = fmaf(t2.y, z, fmaf(-t2.y, v, t2.z));
            const float arg = fmaf(t2.w, z, F) - den;

            float r;
            asm("rcp.approx.f32 %0, %1;" : "=f"(r) : "f"(den));
            float yy = Nz * r;

            const float t  = t2.z * r;                      // bs/den
            float deriv = (t * t) * arg;

            // out-of-range tails (P ~ 6e-7): cold reconstruction
            if (zr != z) {
                const float bsv = t2.z;
                const float y0c = t2.x / bsv;               // C/bs
                const float s0c = F - bsv;
                if (zr < 0.f) {
                    const float x0c = s_x[o];
                    yy = fmaf(xv - x0c, s0c, y0c);
                    deriv = s0c;
                } else {
                    const float s1c = t2.w + s0c;           // E + s0
                    const float bhc = (t1.z + t1.w) / bsv;  // (A+B)/bs
                    const float y1c = y0c + bhc;
                    const float x1c = s_x[o + DD];
                    yy = fmaf(xv - x1c, s1c, y1c);
                    deriv = s1c;
                }
            }
            prod *= deriv;
            yv[i] = yy;
        }

        *(float4*)(y_out + (unsigned)row * DD + 4 * lane) =
            make_float4(yv[0], yv[1], yv[2], yv[3]);

        // one LG2 per 4 elements, then warp-sum; scale by ln2 once per row
        float ls = __log2f(prod);
        #pragma unroll
        for (int off = 16; off; off >>= 1)
            ls += __shfl_xor_sync(0xffffffffu, ls, off);
        if (lane == 0) ld_out[row] = ls * LN2;
    }
}

extern "C" void kernel_launch(void* const* d_in, const int* in_sizes, int n_in,
                              void* d_out, int out_size)
{
    const float* x  = (const float*)d_in[0];
    const float* sp = (const float*)d_in[1];
    const int n_rows = in_sizes[0] / DD;

    float* y_out  = (float*)d_out;
    float* ld_out = (float*)d_out + (size_t)n_rows * DD;

    cudaFuncSetAttribute(rqs_kernel, cudaFuncAttributeMaxDynamicSharedMemorySize,
                         SMEM_BYTES);
    rqs_kernel<<<NBLOCKS, NTHREADS, SMEM_BYTES>>>(x, sp, y_out, ld_out, n_rows);
}

// round 14
// speedup vs baseline: 1.5615x; 1.0178x over previous
#include <cuda_runtime.h>
#include <cstdint>

#define DD 128
#define KK 32
#define NTHREADS 768
#define NBLOCKS 296

// ---- shared memory layout (bytes) ----
// Dim slots swizzled: logical dim d -> slot sd=(d&3)*32+(d>>2); lane owns
// logical dims 4*lane..4*lane+3 -> hot slot = 32*i+lane (bank=lane, cf).
// s_x : float [33][128] knot x positions (binary search + cold tails)
// T1  : float4[32][128] {ib, J=-x0*ib, A, B}
// T2  : float2[32][128] {C, R}
// y = (A z^2 + B z + C) / (1 + R(z - z^2)),  deriv = ib (N'D - N D') / D^2
// Total 112.5KB/block -> 2 blocks (48 warps) per SM.
#define SX_OFF 0
#define T1_OFF 16896
#define T2_OFF (T1_OFF + 32 * DD * 16)
#define SMEM_BYTES (T2_OFF + 32 * DD * 8)

__global__ void __launch_bounds__(NTHREADS, 2)
rqs_kernel(const float* __restrict__ x,
           const float* __restrict__ sp,
           float* __restrict__ y_out,
           float* __restrict__ ld_out,
           int n_rows)
{
    extern __shared__ char smem_raw[];
    float*  s_x  = (float*)(smem_raw + SX_OFF);
    float4* s_T1 = (float4*)(smem_raw + T1_OFF);
    float2* s_T2 = (float2*)(smem_raw + T2_OFF);

    const int tid = threadIdx.x;
    const float TOTAL_M = 10.0f - KK * 1e-4f;
    const float OFFS = 0.5411666430f;  // log(expm1(1 - 1e-4))

    // ---- per-block table build: one thread per dim, streaming ----
    if (tid < DD) {
        const int d = tid;
        const int sd = (d & 3) * 32 + (d >> 2);
        const float* uw = sp + d * (3 * KK + 1);
        const float* uh = uw + KK;
        const float* us = uw + 2 * KK;

        float mw = -1e30f, mh = -1e30f;
        #pragma unroll 1
        for (int k = 0; k < KK; k++) { mw = fmaxf(mw, uw[k]); mh = fmaxf(mh, uh[k]); }
        float sw = 0.f, sh = 0.f;
        #pragma unroll 1
        for (int k = 0; k < KK; k++) { sw += __expf(uw[k] - mw); sh += __expf(uh[k] - mh); }
        const float scw = TOTAL_M / sw;
        const float sch = TOTAL_M / sh;

        float x0 = -5.0f, y0 = -5.0f;
        float v0 = us[0] + OFFS;
        float s0 = fmaxf(v0, 0.f) + __logf(1.f + __expf(-fabsf(v0))) + 1e-4f;
        s_x[sd] = x0;

        #pragma unroll 1
        for (int k = 0; k < KK; k++) {
            const float w = __expf(uw[k] - mw) * scw + 1e-4f;
            const float h = __expf(uh[k] - mh) * sch + 1e-4f;
            const float x1 = x0 + w;
            const float y1 = y0 + h;
            const float vk = us[k + 1] + OFFS;
            const float s1 = fmaxf(vk, 0.f) + __logf(1.f + __expf(-fabsf(vk))) + 1e-4f;

            const float wd = x1 - x0;          // match reference re-diff
            const float ib = 1.0f / wd;
            const float bh = y1 - y0;
            const float bs = bh / wd;
            const float Rp = ((s0 + s1) - 2.0f * bs) / bs;   // R' = R/bs
            const float p  = s0 / bs;

            const float B = y0 * Rp + bh * p;
            const float A = bh - y0 * Rp - bh * p;
            const float C = y0;
            const float J = -x0 * ib;

            s_x[(k + 1) * DD + sd] = x1;
            s_T1[k * DD + sd] = make_float4(ib, J, A, B);
            s_T2[k * DD + sd] = make_float2(C, Rp);

            x0 = x1; y0 = y1; s0 = s1;
        }
    }
    __syncthreads();

    // ---- main loop: one warp per row; lane owns logical dims 4*lane+i ----
    const int lane = tid & 31;
    const int warp = (blockIdx.x * NTHREADS + tid) >> 5;
    const int nwarps = NBLOCKS * (NTHREADS >> 5);
    const float LN2 = 0.69314718055994531f;

    for (int row = warp; row < n_rows; row += nwarps) {
        const float4 xin = *(const float4*)(x + (unsigned)row * DD + 4 * lane);
        const float xa[4] = {xin.x, xin.y, xin.z, xin.w};
        float yv[4];
        float prod = 1.0f;

        #pragma unroll
        for (int i = 0; i < 4; i++) {
            const int slot = 32 * i + lane;
            const float xv = xa[i];

            // binary search: largest idx with x_pos[idx] <= xv, idx in [0,31]
            int idx = 0;
            #pragma unroll
            for (int step = 16; step; step >>= 1) {
                if (xv >= s_x[(idx + step) * DD + slot]) idx += step;
            }
            const int o = idx * DD + slot;

            // fetch: LDS.128 + LDS.64
            const float4 t1 = s_T1[o];   // {ib, J, A, B}
            const float2 t2 = s_T2[o];   // {C, R}
            const float A = t1.z, B = t1.w, C = t2.x, R = t2.y;

            const float zr = fmaf(xv, t1.x, t1.y);          // (xv-x0)*ib
            const float z  = fminf(fmaxf(zr, 0.f), 1.f);
            const float zw = z - z * z;                     // z(1-z)

            const float D  = fmaf(R, zw, 1.0f);
            const float N  = fmaf(fmaf(A, z, B), z, C);
            const float Np = fmaf(A, z, fmaf(A, z, B));     // 2Az + B
            const float Dp = R * fmaf(-2.0f, z, 1.0f);      // R(1-2z)

            float r;
            asm("rcp.approx.f32 %0, %1;" : "=f"(r) : "f"(D));
            float yy = N * r;

            const float q  = fmaf(Np, D, -(N * Dp));
            const float r2 = r * r;
            float deriv = (t1.x * q) * r2;                  // ib q / D^2

            // out-of-range tails (P ~ 6e-7): cold reconstruction
            if (zr != z) {
                if (zr < 0.f) {
                    const float s0c = t1.x * fmaf(-C, R, B);        // ib(B - CR)
                    const float x0c = s_x[o];
                    yy = fmaf(xv - x0c, s0c, C);                    // y0 = C
                    deriv = s0c;
                } else {
                    const float y1c = A + B + C;
                    const float s1c = t1.x * fmaf(y1c, R, A + A + B);
                    const float x1c = s_x[o + DD];
                    yy = fmaf(xv - x1c, s1c, y1c);
                    deriv = s1c;
                }
            }
            prod *= deriv;
            yv[i] = yy;
        }

        *(float4*)(y_out + (unsigned)row * DD + 4 * lane) =
            make_float4(yv[0], yv[1], yv[2], yv[3]);

        // one LG2 per 4 elements, then warp-sum; scale by ln2 once per row
        float ls = __log2f(prod);
        #pragma unroll
        for (int off = 16; off; off >>= 1)
            ls += __shfl_xor_sync(0xffffffffu, ls, off);
        if (lane == 0) ld_out[row] = ls * LN2;
    }
}

extern "C" void kernel_launch(void* const* d_in, const int* in_sizes, int n_in,
                              void* d_out, int out_size)
{
    const float* x  = (const float*)d_in[0];
    const float* sp = (const float*)d_in[1];
    const int n_rows = in_sizes[0] / DD;

    float* y_out  = (float*)d_out;
    float* ld_out = (float*)d_out + (size_t)n_rows * DD;

    cudaFuncSetAttribute(rqs_kernel, cudaFuncAttributeMaxDynamicSharedMemorySize,
                         SMEM_BYTES);
    rqs_kernel<<<NBLOCKS, NTHREADS, SMEM_BYTES>>>(x, sp, y_out, ld_out, n_rows);
}